// round 7
// baseline (speedup 1.0000x reference)
#include <cuda_runtime.h>
#include <cuda_bf16.h>
#include <math.h>

#define BATCH_N 32768
#define IN_DIM  1024
#define ATTN_D  128
#define OUT_D   1024
#define NHEADS  8

#define KT      32
#define PADE    40                 /* bf16 elems per smem row (32 data + 8 pad) */
#define ROWB    (PADE * 2)         /* 80 bytes per row */
#define TILE_B  (128 * ROWB)       /* 10240 bytes per tile */
#define BUF_B   (4 * TILE_B)       /* Ahi, Alo, Bhi, Blo = 40960 */
#define SMEM_MAIN  (2 * BUF_B)     /* double buffered = 81920 */
#define SMEM_TOTAL (SMEM_MAIN + 4096)

// Scratch (cudaMalloc forbidden -> device globals)
__device__ float g_q[(size_t)BATCH_N * ATTN_D];
__device__ float g_dot[(size_t)BATCH_N * NHEADS];
__device__ float g_attn[(size_t)BATCH_N * NHEADS];

__device__ __forceinline__ unsigned smem_u32(const void* p) {
    return (unsigned)__cvta_generic_to_shared(p);
}

__device__ __forceinline__ void ldsm_x4(unsigned* r, unsigned addr) {
    asm volatile("ldmatrix.sync.aligned.m8n8.x4.shared.b16 {%0,%1,%2,%3}, [%4];"
                 : "=r"(r[0]), "=r"(r[1]), "=r"(r[2]), "=r"(r[3]) : "r"(addr));
}

__device__ __forceinline__ void mma_bf16(float* d, const unsigned* a, const unsigned* b) {
    asm volatile(
        "mma.sync.aligned.m16n8k16.row.col.f32.bf16.bf16.f32 "
        "{%0,%1,%2,%3}, {%4,%5,%6,%7}, {%8,%9}, {%0,%1,%2,%3};"
        : "+f"(d[0]), "+f"(d[1]), "+f"(d[2]), "+f"(d[3])
        : "r"(a[0]), "r"(a[1]), "r"(a[2]), "r"(a[3]), "r"(b[0]), "r"(b[1]));
}

// fp32x4 -> (4 bf16 hi, 4 bf16 lo residual), each packed as uint2
__device__ __forceinline__ void split4(float4 v, uint2& hi, uint2& lo) {
    __nv_bfloat162 h01 = __floats2bfloat162_rn(v.x, v.y);
    __nv_bfloat162 h23 = __floats2bfloat162_rn(v.z, v.w);
    float r0 = v.x - __bfloat162float(h01.x);
    float r1 = v.y - __bfloat162float(h01.y);
    float r2 = v.z - __bfloat162float(h23.x);
    float r3 = v.w - __bfloat162float(h23.y);
    __nv_bfloat162 l01 = __floats2bfloat162_rn(r0, r1);
    __nv_bfloat162 l23 = __floats2bfloat162_rn(r2, r3);
    hi.x = *(unsigned*)&h01; hi.y = *(unsigned*)&h23;
    lo.x = *(unsigned*)&l01; lo.y = *(unsigned*)&l23;
}

// MODE 0: Q gemm (N=128)            out = g_q,   aux unused
// MODE 1: K gemm + q.k dot epilogue  out = g_dot, aux = g_q
// MODE 2: V gemm, A scaled by attn   out = d_out, aux = g_attn
template <int MODE, int NKT>
__global__ void __launch_bounds__(256, 1)
gemm_kernel(const float* __restrict__ A, const float* __restrict__ B,
            const float* __restrict__ bias, const float* __restrict__ aux,
            float* __restrict__ out) {
    extern __shared__ char smem[];
    const int tid  = threadIdx.x;
    const int warp = tid >> 5, lane = tid & 31;
    const int bm = blockIdx.x;
    const int bn = blockIdx.y;
    const int rowBase = bm * 128;

    float* attnS = (float*)(smem + SMEM_MAIN);  // MODE 2: 128x8 attn cache
    float* sdot  = (float*)(smem + SMEM_MAIN);  // MODE 1: per-row dot reduce

    if (MODE == 1) { if (tid < 128) sdot[tid] = 0.f; }
    if (MODE == 2) {
        for (int i = tid; i < 128 * NHEADS; i += 256)
            attnS[i] = aux[(size_t)(rowBase + (i >> 3)) * NHEADS + (i & 7)];
    }

    const int srow = tid >> 3;          // 0..31
    const int scol = (tid & 7) * 4;     // 0..28 step 4
    const size_t aRowOff = (size_t)(rowBase + srow) * IN_DIM;
    const size_t bRowOff = (size_t)((MODE == 0 ? 0 : bn * 128) + srow) * IN_DIM;

    float4 ra[4], rb[4];

    auto LDG = [&](int t) {
        const int kg  = t * KT;
        const int kin = kg & (IN_DIM - 1);
        const float* ap = A + aRowOff + kin + scol;
        const float* bp = B + bRowOff + kin + scol;
        if (MODE == 2) bp += (size_t)(kg >> 10) * OUT_D * IN_DIM;
#pragma unroll
        for (int i = 0; i < 4; i++) {
            ra[i] = *(const float4*)(ap + (size_t)i * 32 * IN_DIM);
            rb[i] = *(const float4*)(bp + (size_t)i * 32 * IN_DIM);
        }
    };

    auto STS = [&](int t) {
        char* buf = smem + (t & 1) * BUF_B;
        const int h = (t * KT) >> 10;
#pragma unroll
        for (int i = 0; i < 4; i++) {
            float4 v = ra[i];
            if (MODE == 2) {
                float s = attnS[(srow + 32 * i) * NHEADS + h];
                v.x *= s; v.y *= s; v.z *= s; v.w *= s;
            }
            uint2 hi, lo;
            const int off = (srow + 32 * i) * ROWB + scol * 2;
            split4(v, hi, lo);
            *(uint2*)(buf + off)              = hi;   // A hi
            *(uint2*)(buf + TILE_B + off)     = lo;   // A lo
            split4(rb[i], hi, lo);
            *(uint2*)(buf + 2 * TILE_B + off) = hi;   // B hi
            *(uint2*)(buf + 3 * TILE_B + off) = lo;   // B lo
        }
    };

    const int wm = (warp >> 2) * 64;
    const int wn = (warp & 3) * 32;
    const unsigned lrow   = lane & 15;
    const unsigned lcolB  = (lane >> 4) * 16;   // byte offset within k-step

    float acc[4][4][4];
#pragma unroll
    for (int a = 0; a < 4; a++)
#pragma unroll
        for (int b = 0; b < 4; b++)
#pragma unroll
            for (int c = 0; c < 4; c++) acc[a][b][c] = 0.f;

    auto COMPUTE = [&](int t) {
        const unsigned base = smem_u32(smem + (t & 1) * BUF_B);
#pragma unroll
        for (int ks = 0; ks < 2; ks++) {
            const unsigned kb = ks * 32 + lcolB;
            unsigned ahi[4][4], alo[4][4], bhi[2][4], blo[2][4];
#pragma unroll
            for (int mf = 0; mf < 4; mf++) {
                unsigned ad = base + (wm + mf * 16 + lrow) * ROWB + kb;
                ldsm_x4(ahi[mf], ad);
                ldsm_x4(alo[mf], ad + TILE_B);
            }
#pragma unroll
            for (int nf2 = 0; nf2 < 2; nf2++) {
                unsigned bd = base + 2 * TILE_B + (wn + nf2 * 16 + lrow) * ROWB + kb;
                ldsm_x4(bhi[nf2], bd);
                ldsm_x4(blo[nf2], bd + TILE_B);
            }
#pragma unroll
            for (int mf = 0; mf < 4; mf++) {
#pragma unroll
                for (int nf = 0; nf < 4; nf++) {
                    unsigned bh[2] = { bhi[nf >> 1][nf & 1], bhi[nf >> 1][(nf & 1) + 2] };
                    unsigned bl[2] = { blo[nf >> 1][nf & 1], blo[nf >> 1][(nf & 1) + 2] };
                    mma_bf16(acc[mf][nf], ahi[mf], bh);   // hi*hi
                    mma_bf16(acc[mf][nf], alo[mf], bh);   // lo*hi
                    mma_bf16(acc[mf][nf], ahi[mf], bl);   // hi*lo
                }
            }
        }
    };

    LDG(0);
    __syncthreads();     // attnS / sdot ready
    STS(0);
    __syncthreads();
    for (int t = 0; t < NKT; t++) {
        if (t + 1 < NKT) LDG(t + 1);
        COMPUTE(t);
        if (t + 1 < NKT) {
            STS(t + 1);
            __syncthreads();
        }
    }

    // ---- epilogue ----
    const int erow0 = wm + (lane >> 2);
    const int ecol0 = wn + (lane & 3) * 2;

    if (MODE == 0) {
#pragma unroll
        for (int mf = 0; mf < 4; mf++)
#pragma unroll
            for (int e2 = 0; e2 < 2; e2++) {
                int r = rowBase + erow0 + mf * 16 + e2 * 8;
#pragma unroll
                for (int nf = 0; nf < 4; nf++) {
                    int c = ecol0 + nf * 8;
                    float2 v;
                    v.x = acc[mf][nf][e2 * 2 + 0] + bias[c];
                    v.y = acc[mf][nf][e2 * 2 + 1] + bias[c + 1];
                    *(float2*)(out + (size_t)r * ATTN_D + c) = v;
                }
            }
    } else if (MODE == 1) {
        // dot[b, h] = sum_a (keys + bk) * q ; this CTA covers the full attn-dim of head bn
#pragma unroll
        for (int mf = 0; mf < 4; mf++)
#pragma unroll
            for (int e2 = 0; e2 < 2; e2++) {
                int rl = erow0 + mf * 16 + e2 * 8;
                int rg = rowBase + rl;
                float s = 0.f;
#pragma unroll
                for (int nf = 0; nf < 4; nf++) {
                    int c = ecol0 + nf * 8;
                    float q0 = aux[(size_t)rg * ATTN_D + c];
                    float q1 = aux[(size_t)rg * ATTN_D + c + 1];
                    s += (acc[mf][nf][e2 * 2 + 0] + bias[bn * ATTN_D + c])     * q0;
                    s += (acc[mf][nf][e2 * 2 + 1] + bias[bn * ATTN_D + c + 1]) * q1;
                }
                atomicAdd(&sdot[rl], s);
            }
        __syncthreads();
        if (tid < 128)
            out[(size_t)(rowBase + tid) * NHEADS + bn] = sdot[tid];
    } else {
        // out += sum_h attn[b,h]*bv[h,c]
#pragma unroll
        for (int nf = 0; nf < 4; nf++) {
            int c = bn * 128 + ecol0 + nf * 8;
            float bv0[NHEADS], bv1[NHEADS];
#pragma unroll
            for (int h = 0; h < NHEADS; h++) {
                bv0[h] = bias[h * OUT_D + c];
                bv1[h] = bias[h * OUT_D + c + 1];
            }
#pragma unroll
            for (int mf = 0; mf < 4; mf++)
#pragma unroll
                for (int e2 = 0; e2 < 2; e2++) {
                    int rl = erow0 + mf * 16 + e2 * 8;
                    int rg = rowBase + rl;
                    float b0 = 0.f, b1 = 0.f;
#pragma unroll
                    for (int h = 0; h < NHEADS; h++) {
                        float at = attnS[rl * NHEADS + h];
                        b0 += at * bv0[h];
                        b1 += at * bv1[h];
                    }
                    float2 v;
                    v.x = acc[mf][nf][e2 * 2 + 0] + b0;
                    v.y = acc[mf][nf][e2 * 2 + 1] + b1;
                    *(float2*)(out + (size_t)rg * OUT_D + c) = v;
                }
        }
    }
}

__global__ void softmax_kernel(const float* __restrict__ dot, float* __restrict__ attn) {
    int b = blockIdx.x * blockDim.x + threadIdx.x;
    if (b >= BATCH_N) return;
    const float sc = 0.08838834764831845f;  // 1/sqrt(128)
    float d[NHEADS], m = -1e30f;
#pragma unroll
    for (int h = 0; h < NHEADS; h++) { d[h] = dot[b * NHEADS + h] * sc; m = fmaxf(m, d[h]); }
    float s = 0.f;
#pragma unroll
    for (int h = 0; h < NHEADS; h++) { d[h] = __expf(d[h] - m); s += d[h]; }
    float inv = 1.f / s;
#pragma unroll
    for (int h = 0; h < NHEADS; h++) attn[b * NHEADS + h] = d[h] * inv;
}

extern "C" void kernel_launch(void* const* d_in, const int* in_sizes, int n_in,
                              void* d_out, int out_size) {
    const float* x  = (const float*)d_in[0];
    const float* Wq = (const float*)d_in[1];
    const float* bq = (const float*)d_in[2];
    const float* Wk = (const float*)d_in[3];
    const float* bk = (const float*)d_in[4];
    const float* Wv = (const float*)d_in[5];
    const float* bv = (const float*)d_in[6];
    float* out = (float*)d_out;

    float *qp, *dp, *ap;
    cudaGetSymbolAddress((void**)&qp, g_q);
    cudaGetSymbolAddress((void**)&dp, g_dot);
    cudaGetSymbolAddress((void**)&ap, g_attn);

    cudaFuncSetAttribute(gemm_kernel<0, 32>,  cudaFuncAttributeMaxDynamicSharedMemorySize, SMEM_TOTAL);
    cudaFuncSetAttribute(gemm_kernel<1, 32>,  cudaFuncAttributeMaxDynamicSharedMemorySize, SMEM_TOTAL);
    cudaFuncSetAttribute(gemm_kernel<2, 256>, cudaFuncAttributeMaxDynamicSharedMemorySize, SMEM_TOTAL);

    gemm_kernel<0, 32><<<dim3(BATCH_N / 128, 1), 256, SMEM_TOTAL>>>(x, Wq, bq, nullptr, qp);
    gemm_kernel<1, 32><<<dim3(BATCH_N / 128, NHEADS), 256, SMEM_TOTAL>>>(x, Wk, bk, qp, dp);
    softmax_kernel<<<BATCH_N / 256, 256>>>(dp, ap);
    gemm_kernel<2, 256><<<dim3(BATCH_N / 128, NHEADS), 256, SMEM_TOTAL>>>(x, Wv, bv, ap, out);
}

// round 11
// speedup vs baseline: 1.0751x; 1.0751x over previous
#include <cuda_runtime.h>
#include <cuda_bf16.h>
#include <math.h>
#include <stdint.h>

#define BATCH_N 32768
#define IN_DIM  1024
#define ATTN_D  128
#define OUT_D   1024
#define NHEADS  8

#define KT      32
#define PADE    40                 /* bf16 elems per smem row (32 data + 8 pad) */
#define ROWB    (PADE * 2)         /* 80 bytes per row */
#define TILE_B  (128 * ROWB)       /* 10240 bytes */
#define BUF_B   (4 * TILE_B)       /* Ahi, Alo, Bhi, Blo = 40960 */
#define NSTAGE  4
#define SMEM_MAIN  (NSTAGE * BUF_B)        /* 163840 */
#define SMEM_TOTAL (SMEM_MAIN + 8192)

// ---------------- device-global scratch (no cudaMalloc allowed) --------
__device__ float g_q[(size_t)BATCH_N * ATTN_D];
__device__ float g_dot[BATCH_N * NHEADS];
__device__ float g_attn[BATCH_N * NHEADS];
__device__ uint2 g_xhi[(size_t)BATCH_N * IN_DIM / 4];
__device__ uint2 g_xlo[(size_t)BATCH_N * IN_DIM / 4];
__device__ uint2 g_wqhi[ATTN_D * IN_DIM / 4];
__device__ uint2 g_wqlo[ATTN_D * IN_DIM / 4];
__device__ uint2 g_wkhi[NHEADS * ATTN_D * IN_DIM / 4];
__device__ uint2 g_wklo[NHEADS * ATTN_D * IN_DIM / 4];
__device__ uint2 g_wvhi[(size_t)NHEADS * OUT_D * IN_DIM / 4];
__device__ uint2 g_wvlo[(size_t)NHEADS * OUT_D * IN_DIM / 4];

__device__ __forceinline__ unsigned smem_u32(const void* p) {
    return (unsigned)__cvta_generic_to_shared(p);
}

// fp32x4 -> (4 bf16 hi, 4 bf16 lo residual) packed as uint2 each
__device__ __forceinline__ void split4(float4 v, uint2& hi, uint2& lo) {
    __nv_bfloat162 h01 = __floats2bfloat162_rn(v.x, v.y);
    __nv_bfloat162 h23 = __floats2bfloat162_rn(v.z, v.w);
    float r0 = v.x - __bfloat162float(h01.x);
    float r1 = v.y - __bfloat162float(h01.y);
    float r2 = v.z - __bfloat162float(h23.x);
    float r3 = v.w - __bfloat162float(h23.y);
    __nv_bfloat162 l01 = __floats2bfloat162_rn(r0, r1);
    __nv_bfloat162 l23 = __floats2bfloat162_rn(r2, r3);
    hi.x = *(unsigned*)&h01; hi.y = *(unsigned*)&h23;
    lo.x = *(unsigned*)&l01; lo.y = *(unsigned*)&l23;
}

__global__ void split_kernel(const float4* __restrict__ src, uint2* __restrict__ hi,
                             uint2* __restrict__ lo, int n4) {
    int i = blockIdx.x * blockDim.x + threadIdx.x;
    if (i < n4) {
        uint2 h, l;
        split4(src[i], h, l);
        hi[i] = h; lo[i] = l;
    }
}

__device__ __forceinline__ void ldsm_x4(unsigned* r, unsigned addr) {
    asm volatile("ldmatrix.sync.aligned.m8n8.x4.shared.b16 {%0,%1,%2,%3}, [%4];"
                 : "=r"(r[0]), "=r"(r[1]), "=r"(r[2]), "=r"(r[3]) : "r"(addr));
}
__device__ __forceinline__ void mma_bf16(float* d, const unsigned* a, const unsigned* b) {
    asm volatile(
        "mma.sync.aligned.m16n8k16.row.col.f32.bf16.bf16.f32 "
        "{%0,%1,%2,%3}, {%4,%5,%6,%7}, {%8,%9}, {%0,%1,%2,%3};"
        : "+f"(d[0]), "+f"(d[1]), "+f"(d[2]), "+f"(d[3])
        : "r"(a[0]), "r"(a[1]), "r"(a[2]), "r"(a[3]), "r"(b[0]), "r"(b[1]));
}

#define CP16(sm, gp) asm volatile("cp.async.cg.shared.global [%0], [%1], 16;" \
                                  :: "r"(sm), "l"(gp) : "memory")
#define CP_COMMIT()  asm volatile("cp.async.commit_group;" ::: "memory")
#define CP_WAIT2()   asm volatile("cp.async.wait_group 2;" ::: "memory")

// MODE 0: Q gemm (N=128)             out=g_q
// MODE 1: K gemm + q.k dot epilogue  out=g_dot, aux=g_q
// MODE 2: V gemm, per-head acc merge out=d_out, aux=g_attn   (NKT=256)
template <int MODE, int NKT>
__global__ void __launch_bounds__(256, 1)
gemm_kernel(const char* __restrict__ Ahi, const char* __restrict__ Alo,
            const char* __restrict__ Bhi, const char* __restrict__ Blo,
            const float* __restrict__ bias, const float* __restrict__ aux,
            float* __restrict__ out) {
    extern __shared__ char smem[];
    const unsigned sbase = smem_u32(smem);
    const int tid  = threadIdx.x;
    const int warp = tid >> 5, lane = tid & 31;
    const int bm = blockIdx.x;
    const int bn = blockIdx.y;
    const int rowBase = bm * 128;
    const int bRowBase = (MODE == 0) ? 0 : bn * 128;

    float* attnS = (float*)(smem + SMEM_MAIN);   // MODE 2: 128x8
    float* sdot  = (float*)(smem + SMEM_MAIN);   // MODE 1: 128 floats

    if (MODE == 1) { if (tid < 128) sdot[tid] = 0.f; }
    if (MODE == 2) {
        for (int i = tid; i < 128 * NHEADS; i += 256)
            attnS[i] = aux[(size_t)(rowBase + (i >> 3)) * NHEADS + (i & 7)];
    }

    // per-thread copy slots: 2 chunks of 16B per tile
    const int row0 = tid >> 2,          c0 = tid & 3;
    const int row1 = (tid + 256) >> 2,  c1 = (tid + 256) & 3;
    const size_t aOff0 = ((size_t)(rowBase + row0) * IN_DIM + c0 * 8) * 2;
    const size_t aOff1 = ((size_t)(rowBase + row1) * IN_DIM + c1 * 8) * 2;
    const size_t bOff0 = ((size_t)(bRowBase + row0) * IN_DIM + c0 * 8) * 2;
    const size_t bOff1 = ((size_t)(bRowBase + row1) * IN_DIM + c1 * 8) * 2;
    const unsigned sm0 = row0 * ROWB + c0 * 16;
    const unsigned sm1 = row1 * ROWB + c1 * 16;

    auto LOAD = [&](int s) {
        if (s < NKT) {
            const unsigned sb = sbase + (s & 3) * BUF_B;
            const size_t ka = (size_t)((s * KT) & (IN_DIM - 1)) * 2;
            const size_t kb = (MODE == 2)
                ? ka + (size_t)(s >> 5) * ((size_t)OUT_D * IN_DIM * 2) : ka;
            CP16(sb + sm0,              Ahi + aOff0 + ka);
            CP16(sb + sm1,              Ahi + aOff1 + ka);
            CP16(sb + TILE_B + sm0,     Alo + aOff0 + ka);
            CP16(sb + TILE_B + sm1,     Alo + aOff1 + ka);
            CP16(sb + 2 * TILE_B + sm0, Bhi + bOff0 + kb);
            CP16(sb + 2 * TILE_B + sm1, Bhi + bOff1 + kb);
            CP16(sb + 3 * TILE_B + sm0, Blo + bOff0 + kb);
            CP16(sb + 3 * TILE_B + sm1, Blo + bOff1 + kb);
        }
        CP_COMMIT();
    };

    const int wm = (warp >> 2) * 64;
    const int wn = (warp & 3) * 32;
    const unsigned lrow  = lane & 15;
    const unsigned lcolB = (lane >> 4) * 16;

    float acc[4][4][4];           // per-head (MODE 2) or final (MODE 0/1)
    float accT[4][4][4];          // MODE 2 final
#pragma unroll
    for (int a = 0; a < 4; a++)
#pragma unroll
        for (int b = 0; b < 4; b++)
#pragma unroll
            for (int c = 0; c < 4; c++) { acc[a][b][c] = 0.f; if (MODE == 2) accT[a][b][c] = 0.f; }

    auto COMPUTE = [&](int t) {
        const unsigned base = sbase + (t & 3) * BUF_B;
#pragma unroll
        for (int ks = 0; ks < 2; ks++) {
            const unsigned kb = ks * 32 + lcolB;
            unsigned ahi[4][4], alo[4][4], bhi[2][4], blo[2][4];
#pragma unroll
            for (int mf = 0; mf < 4; mf++) {
                unsigned ad = base + (wm + mf * 16 + lrow) * ROWB + kb;
                ldsm_x4(ahi[mf], ad);
                ldsm_x4(alo[mf], ad + TILE_B);
            }
#pragma unroll
            for (int nf2 = 0; nf2 < 2; nf2++) {
                unsigned bd = base + 2 * TILE_B + (wn + nf2 * 16 + lrow) * ROWB + kb;
                ldsm_x4(bhi[nf2], bd);
                ldsm_x4(blo[nf2], bd + TILE_B);
            }
#pragma unroll
            for (int mf = 0; mf < 4; mf++)
#pragma unroll
                for (int nf = 0; nf < 4; nf++) {
                    unsigned bh[2] = { bhi[nf >> 1][nf & 1], bhi[nf >> 1][(nf & 1) + 2] };
                    unsigned bl[2] = { blo[nf >> 1][nf & 1], blo[nf >> 1][(nf & 1) + 2] };
                    mma_bf16(acc[mf][nf], ahi[mf], bh);
                    mma_bf16(acc[mf][nf], alo[mf], bh);
                    mma_bf16(acc[mf][nf], ahi[mf], bl);
                }
        }
    };

    LOAD(0); LOAD(1); LOAD(2);

    for (int s = 0; s < NKT; s++) {
        CP_WAIT2();
        __syncthreads();
        COMPUTE(s);
        if (MODE == 2 && ((s & 31) == 31)) {
            const int h = s >> 5;
#pragma unroll
            for (int mf = 0; mf < 4; mf++)
#pragma unroll
                for (int eh = 0; eh < 2; eh++) {
                    const float sc = attnS[(wm + (lane >> 2) + mf * 16 + eh * 8) * NHEADS + h];
#pragma unroll
                    for (int nf = 0; nf < 4; nf++) {
                        accT[mf][nf][eh * 2 + 0] += sc * acc[mf][nf][eh * 2 + 0];
                        accT[mf][nf][eh * 2 + 1] += sc * acc[mf][nf][eh * 2 + 1];
                        acc[mf][nf][eh * 2 + 0] = 0.f;
                        acc[mf][nf][eh * 2 + 1] = 0.f;
                    }
                }
        }
        LOAD(s + 3);
    }

    // ---- epilogue ----
    const int erow0 = wm + (lane >> 2);
    const int ecol0 = wn + (lane & 3) * 2;

    if (MODE == 0) {
#pragma unroll
        for (int mf = 0; mf < 4; mf++)
#pragma unroll
            for (int e2 = 0; e2 < 2; e2++) {
                int r = rowBase + erow0 + mf * 16 + e2 * 8;
#pragma unroll
                for (int nf = 0; nf < 4; nf++) {
                    int c = ecol0 + nf * 8;
                    float2 v;
                    v.x = acc[mf][nf][e2 * 2 + 0] + bias[c];
                    v.y = acc[mf][nf][e2 * 2 + 1] + bias[c + 1];
                    *(float2*)(out + (size_t)r * ATTN_D + c) = v;
                }
            }
    } else if (MODE == 1) {
#pragma unroll
        for (int mf = 0; mf < 4; mf++)
#pragma unroll
            for (int e2 = 0; e2 < 2; e2++) {
                int rl = erow0 + mf * 16 + e2 * 8;
                int rg = rowBase + rl;
                float s = 0.f;
#pragma unroll
                for (int nf = 0; nf < 4; nf++) {
                    int c = ecol0 + nf * 8;
                    float q0 = aux[(size_t)rg * ATTN_D + c];
                    float q1 = aux[(size_t)rg * ATTN_D + c + 1];
                    s += (acc[mf][nf][e2 * 2 + 0] + bias[bn * ATTN_D + c])     * q0;
                    s += (acc[mf][nf][e2 * 2 + 1] + bias[bn * ATTN_D + c + 1]) * q1;
                }
                atomicAdd(&sdot[rl], s);
            }
        __syncthreads();
        if (tid < 128)
            out[(size_t)(rowBase + tid) * NHEADS + bn] = sdot[tid];
    } else {
        // out = accT + sum_h attn[b,h]*bv[h,c]
#pragma unroll
        for (int nf = 0; nf < 4; nf++) {
            int c = bn * 128 + ecol0 + nf * 8;
            float bv0[NHEADS], bv1[NHEADS];
#pragma unroll
            for (int h = 0; h < NHEADS; h++) {
                bv0[h] = bias[h * OUT_D + c];
                bv1[h] = bias[h * OUT_D + c + 1];
            }
#pragma unroll
            for (int mf = 0; mf < 4; mf++)
#pragma unroll
                for (int e2 = 0; e2 < 2; e2++) {
                    int rl = erow0 + mf * 16 + e2 * 8;
                    int rg = rowBase + rl;
                    float b0 = 0.f, b1 = 0.f;
#pragma unroll
                    for (int h = 0; h < NHEADS; h++) {
                        float at = attnS[rl * NHEADS + h];
                        b0 += at * bv0[h];
                        b1 += at * bv1[h];
                    }
                    float2 v;
                    v.x = accT[mf][nf][e2 * 2 + 0] + b0;
                    v.y = accT[mf][nf][e2 * 2 + 1] + b1;
                    *(float2*)(out + (size_t)rg * OUT_D + c) = v;
                }
        }
    }
}

__global__ void softmax_kernel(const float* __restrict__ dot, float* __restrict__ attn) {
    int b = blockIdx.x * blockDim.x + threadIdx.x;
    if (b >= BATCH_N) return;
    const float sc = 0.08838834764831845f;
    float d[NHEADS], m = -1e30f;
#pragma unroll
    for (int h = 0; h < NHEADS; h++) { d[h] = dot[b * NHEADS + h] * sc; m = fmaxf(m, d[h]); }
    float s = 0.f;
#pragma unroll
    for (int h = 0; h < NHEADS; h++) { d[h] = __expf(d[h] - m); s += d[h]; }
    float inv = 1.f / s;
#pragma unroll
    for (int h = 0; h < NHEADS; h++) attn[b * NHEADS + h] = d[h] * inv;
}

extern "C" void kernel_launch(void* const* d_in, const int* in_sizes, int n_in,
                              void* d_out, int out_size) {
    const float* x  = (const float*)d_in[0];
    const float* Wq = (const float*)d_in[1];
    const float* bq = (const float*)d_in[2];
    const float* Wk = (const float*)d_in[3];
    const float* bk = (const float*)d_in[4];
    const float* Wv = (const float*)d_in[5];
    const float* bv = (const float*)d_in[6];
    float* out = (float*)d_out;

    float *qp, *dp, *ap;
    cudaGetSymbolAddress((void**)&qp, g_q);
    cudaGetSymbolAddress((void**)&dp, g_dot);
    cudaGetSymbolAddress((void**)&ap, g_attn);
    uint2 *xhi, *xlo, *wqhi, *wqlo, *wkhi, *wklo, *wvhi, *wvlo;
    cudaGetSymbolAddress((void**)&xhi,  g_xhi);
    cudaGetSymbolAddress((void**)&xlo,  g_xlo);
    cudaGetSymbolAddress((void**)&wqhi, g_wqhi);
    cudaGetSymbolAddress((void**)&wqlo, g_wqlo);
    cudaGetSymbolAddress((void**)&wkhi, g_wkhi);
    cudaGetSymbolAddress((void**)&wklo, g_wklo);
    cudaGetSymbolAddress((void**)&wvhi, g_wvhi);
    cudaGetSymbolAddress((void**)&wvlo, g_wvlo);

    cudaFuncSetAttribute(gemm_kernel<0, 32>,  cudaFuncAttributeMaxDynamicSharedMemorySize, SMEM_TOTAL);
    cudaFuncSetAttribute(gemm_kernel<1, 32>,  cudaFuncAttributeMaxDynamicSharedMemorySize, SMEM_TOTAL);
    cudaFuncSetAttribute(gemm_kernel<2, 256>, cudaFuncAttributeMaxDynamicSharedMemorySize, SMEM_TOTAL);

    // pre-split fp32 -> bf16 hi/lo
    {
        int n4;
        n4 = BATCH_N * IN_DIM / 4;
        split_kernel<<<(n4 + 255) / 256, 256>>>((const float4*)x, xhi, xlo, n4);
        n4 = ATTN_D * IN_DIM / 4;
        split_kernel<<<(n4 + 255) / 256, 256>>>((const float4*)Wq, wqhi, wqlo, n4);
        n4 = NHEADS * ATTN_D * IN_DIM / 4;
        split_kernel<<<(n4 + 255) / 256, 256>>>((const float4*)Wk, wkhi, wklo, n4);
        n4 = (int)((size_t)NHEADS * OUT_D * IN_DIM / 4);
        split_kernel<<<(n4 + 255) / 256, 256>>>((const float4*)Wv, wvhi, wvlo, n4);
    }

    gemm_kernel<0, 32><<<dim3(BATCH_N / 128, 1), 256, SMEM_TOTAL>>>(
        (const char*)xhi, (const char*)xlo, (const char*)wqhi, (const char*)wqlo, bq, nullptr, qp);
    gemm_kernel<1, 32><<<dim3(BATCH_N / 128, NHEADS), 256, SMEM_TOTAL>>>(
        (const char*)xhi, (const char*)xlo, (const char*)wkhi, (const char*)wklo, bk, qp, dp);
    softmax_kernel<<<BATCH_N / 256, 256>>>(dp, ap);
    gemm_kernel<2, 256><<<dim3(BATCH_N / 128, NHEADS), 256, SMEM_TOTAL>>>(
        (const char*)xhi, (const char*)xlo, (const char*)wvhi, (const char*)wvlo, bv, ap, out);
}